// round 3
// baseline (speedup 1.0000x reference)
#include <cuda_runtime.h>
#include <cstdint>
#include <math.h>

// Problem constants (B=4, S=2048 -> T=8192 tokens)
#define T_TOK 8192
#define H_DIM 1024
#define F_DIM 4096
#define NEXP  8
#define TOPK  2

#define BM 128
#define BN 128
#define BK 16
#define ASTRIDE 20    // padded row stride (floats) for A smem tile -> conflict-free mma LDS
#define BSTRIDE 136   // padded row stride (floats) for B smem tile -> conflict-free mma LDS

// ---- persistent scratch (device globals: allocation-free kernel_launch) ----
__device__ int   g_count[NEXP];
__device__ int   g_offset[NEXP];
__device__ int   g_perm[NEXP * T_TOK];              // slot ids (t*2+k) grouped by expert
__device__ float g_wslot[T_TOK * TOPK];             // renormalized top-k weight per slot
__device__ float g_hbuf[(size_t)T_TOK * TOPK * F_DIM];  // gelu(x@w1+b1), compact rows
__device__ float g_ybuf[(size_t)T_TOK * TOPK * H_DIM];  // per-slot expert output

// ---------------------------------------------------------------------------
__global__ void zero_counts_kernel() {
    if (threadIdx.x < NEXP) g_count[threadIdx.x] = 0;
}

__global__ void scan_kernel() {
    // single thread: tiny exclusive scan over 8 counts
    int s = 0;
    for (int e = 0; e < NEXP; e++) { g_offset[e] = s; s += g_count[e]; }
}

// Router: one warp per token. logits = x @ router_w + router_b; top-2 of
// softmax == top-2 of logits; renormalized weights via cancelled denominator.
__global__ __launch_bounds__(256)
void router_kernel(const float* __restrict__ x,
                   const float* __restrict__ rw,
                   const float* __restrict__ rb) {
    int warp = (blockIdx.x * blockDim.x + threadIdx.x) >> 5;
    int lane = threadIdx.x & 31;
    if (warp >= T_TOK) return;
    const float* xr = x + (size_t)warp * H_DIM;

    float acc[NEXP];
#pragma unroll
    for (int e = 0; e < NEXP; e++) acc[e] = 0.f;
    for (int h = lane; h < H_DIM; h += 32) {
        float xv = xr[h];
        const float* w = rw + h * NEXP;
#pragma unroll
        for (int e = 0; e < NEXP; e++) acc[e] += xv * w[e];
    }
#pragma unroll
    for (int e = 0; e < NEXP; e++) {
#pragma unroll
        for (int s = 16; s > 0; s >>= 1)
            acc[e] += __shfl_xor_sync(0xffffffffu, acc[e], s);
    }
    if (lane == 0) {
#pragma unroll
        for (int e = 0; e < NEXP; e++) acc[e] += rb[e];
        int e0 = 0;
#pragma unroll
        for (int e = 1; e < NEXP; e++) if (acc[e] > acc[e0]) e0 = e;
        int e1 = (e0 == 0) ? 1 : 0;
#pragma unroll
        for (int e = 0; e < NEXP; e++)
            if (e != e0 && acc[e] > acc[e1]) e1 = e;

        float r  = expf(acc[e1] - acc[e0]);   // <= 1
        float w0 = 1.f / (1.f + r);
        float w1 = r / (1.f + r);

        int s0 = warp * 2, s1 = warp * 2 + 1;
        int p0 = atomicAdd(&g_count[e0], 1);
        g_perm[e0 * T_TOK + p0] = s0;
        g_wslot[s0] = w0;
        int p1 = atomicAdd(&g_count[e1], 1);
        g_perm[e1 * T_TOK + p1] = s1;
        g_wslot[s1] = w1;
    }
}

// ---------------------------------------------------------------------------
__device__ __forceinline__ uint32_t f2tf32(float f) {
    uint32_t u;
    asm("cvt.rna.tf32.f32 %0, %1;" : "=r"(u) : "f"(f));
    return u;
}

__device__ __forceinline__ float gelu_tanh(float v) {
    float v3 = v * v * v;
    float t  = tanhf(0.7978845608028654f * (v + 0.044715f * v3));
    return 0.5f * v * (1.f + t);
}

// Gathered per-expert GEMM, tf32 mma.sync m16n8k8.
// MODE 0: C = gelu(Xgather @ w1[e] + b1[e]) -> g_hbuf (compact rows), KD=H, ND=F
// MODE 1: C = g_hbuf @ w2[e] + b2[e]        -> g_ybuf (scatter to slots), KD=F, ND=H
template<int KD, int MODE>
__global__ __launch_bounds__(256, 2)
void moe_gemm(const float* __restrict__ Xin,
              const float* __restrict__ W,
              const float* __restrict__ bias,
              int ND) {
    const int e    = blockIdx.z;
    const int cnt  = g_count[e];
    const int row0 = blockIdx.y * BM;
    if (row0 >= cnt) return;
    const int col0 = blockIdx.x * BN;
    const int off  = g_offset[e];

    const float* Aglob = (MODE == 0) ? Xin : (const float*)g_hbuf;

    __shared__ uint32_t As[BM * ASTRIDE];
    __shared__ uint32_t Bs[BK * BSTRIDE];

    const int tid  = threadIdx.x;
    const int lane = tid & 31, warp = tid >> 5;
    const int wm = warp & 3, wn = warp >> 2;   // 4 x 2 warp grid, warp tile 32x64
    const int g  = lane >> 2, tg = lane & 3;

    // A staging: thread loads rows (arow, arow+64), 4 floats starting at aseg
    const int arow = tid >> 2;           // 0..63
    const int aseg = (tid & 3) * 4;
    const bool av0 = (row0 + arow) < cnt;
    const bool av1 = (row0 + arow + 64) < cnt;
    long asrc0 = 0, asrc1 = 0;
    if (MODE == 0) {
        if (av0) asrc0 = (long)(g_perm[e * T_TOK + row0 + arow] >> 1) * KD;
        if (av1) asrc1 = (long)(g_perm[e * T_TOK + row0 + arow + 64] >> 1) * KD;
    } else {
        if (av0) asrc0 = (long)(off + row0 + arow) * KD;
        if (av1) asrc1 = (long)(off + row0 + arow + 64) * KD;
    }

    // B staging: thread loads rows (brow, brow+8), 4 floats at bcol
    const int brow = tid >> 5;           // 0..7
    const int bcol = (tid & 31) * 4;
    const float* Wb = W + (size_t)e * KD * ND + col0;

    float c[2][8][4];
#pragma unroll
    for (int i = 0; i < 2; i++)
#pragma unroll
        for (int j = 0; j < 8; j++)
#pragma unroll
            for (int q = 0; q < 4; q++) c[i][j][q] = 0.f;

    float4 ra0, ra1, rbA, rbB;

    auto loadG = [&](int k0) {
        ra0 = av0 ? *(const float4*)(Aglob + asrc0 + k0 + aseg) : make_float4(0, 0, 0, 0);
        ra1 = av1 ? *(const float4*)(Aglob + asrc1 + k0 + aseg) : make_float4(0, 0, 0, 0);
        rbA = *(const float4*)(Wb + (size_t)(k0 + brow) * ND + bcol);
        rbB = *(const float4*)(Wb + (size_t)(k0 + brow + 8) * ND + bcol);
    };
    auto storeS = [&]() {
        uint32_t* p = &As[arow * ASTRIDE + aseg];
        p[0] = f2tf32(ra0.x); p[1] = f2tf32(ra0.y); p[2] = f2tf32(ra0.z); p[3] = f2tf32(ra0.w);
        p = &As[(arow + 64) * ASTRIDE + aseg];
        p[0] = f2tf32(ra1.x); p[1] = f2tf32(ra1.y); p[2] = f2tf32(ra1.z); p[3] = f2tf32(ra1.w);
        p = &Bs[brow * BSTRIDE + bcol];
        p[0] = f2tf32(rbA.x); p[1] = f2tf32(rbA.y); p[2] = f2tf32(rbA.z); p[3] = f2tf32(rbA.w);
        p = &Bs[(brow + 8) * BSTRIDE + bcol];
        p[0] = f2tf32(rbB.x); p[1] = f2tf32(rbB.y); p[2] = f2tf32(rbB.z); p[3] = f2tf32(rbB.w);
    };

    loadG(0);
    const int nk = KD / BK;
    for (int kt = 0; kt < nk; kt++) {
        storeS();
        __syncthreads();
        if (kt + 1 < nk) loadG((kt + 1) * BK);   // prefetch overlaps the MMAs below

#pragma unroll
        for (int kk = 0; kk < BK; kk += 8) {
            uint32_t af[2][4], bf[8][2];
#pragma unroll
            for (int mf = 0; mf < 2; mf++) {
                int rb_ = wm * 32 + mf * 16;
                af[mf][0] = As[(rb_ + g)     * ASTRIDE + kk + tg];
                af[mf][1] = As[(rb_ + g + 8) * ASTRIDE + kk + tg];
                af[mf][2] = As[(rb_ + g)     * ASTRIDE + kk + tg + 4];
                af[mf][3] = As[(rb_ + g + 8) * ASTRIDE + kk + tg + 4];
            }
#pragma unroll
            for (int nf = 0; nf < 8; nf++) {
                int cb = wn * 64 + nf * 8;
                bf[nf][0] = Bs[(kk + tg)     * BSTRIDE + cb + g];
                bf[nf][1] = Bs[(kk + tg + 4) * BSTRIDE + cb + g];
            }
#pragma unroll
            for (int mf = 0; mf < 2; mf++)
#pragma unroll
                for (int nf = 0; nf < 8; nf++)
                    asm volatile(
                        "mma.sync.aligned.m16n8k8.row.col.f32.tf32.tf32.f32 "
                        "{%0,%1,%2,%3}, {%4,%5,%6,%7}, {%8,%9}, {%0,%1,%2,%3};\n"
                        : "+f"(c[mf][nf][0]), "+f"(c[mf][nf][1]),
                          "+f"(c[mf][nf][2]), "+f"(c[mf][nf][3])
                        : "r"(af[mf][0]), "r"(af[mf][1]), "r"(af[mf][2]), "r"(af[mf][3]),
                          "r"(bf[nf][0]), "r"(bf[nf][1]));
        }
        __syncthreads();
    }

    // Epilogue. c frag layout: rows (g, g+8), cols (2*tg, 2*tg+1).
#pragma unroll
    for (int mf = 0; mf < 2; mf++) {
#pragma unroll
        for (int half = 0; half < 2; half++) {
            int r    = wm * 32 + mf * 16 + g + half * 8;
            int grow = row0 + r;
            if (grow >= cnt) continue;
            long drow;
            if (MODE == 0) drow = (long)(off + grow) * F_DIM;
            else           drow = (long)g_perm[e * T_TOK + grow] * H_DIM;
#pragma unroll
            for (int nf = 0; nf < 8; nf++) {
                int col  = col0 + wn * 64 + nf * 8 + 2 * tg;
                float v0 = c[mf][nf][half * 2 + 0] + bias[e * ND + col];
                float v1 = c[mf][nf][half * 2 + 1] + bias[e * ND + col + 1];
                if (MODE == 0) {
                    float2 o = make_float2(gelu_tanh(v0), gelu_tanh(v1));
                    *(float2*)&g_hbuf[drow + col] = o;
                } else {
                    float2 o = make_float2(v0, v1);
                    *(float2*)&g_ybuf[drow + col] = o;
                }
            }
        }
    }
}

// ---------------------------------------------------------------------------
__global__ __launch_bounds__(256)
void combine_kernel(float* __restrict__ out) {
    int idx = blockIdx.x * blockDim.x + threadIdx.x;
    if (idx >= T_TOK * H_DIM) return;
    int t = idx >> 10;           // H_DIM = 1024
    int h = idx & 1023;
    float v = g_wslot[2 * t]     * g_ybuf[(size_t)(2 * t)     * H_DIM + h]
            + g_wslot[2 * t + 1] * g_ybuf[(size_t)(2 * t + 1) * H_DIM + h];
    out[idx] = v;
}

// ---------------------------------------------------------------------------
extern "C" void kernel_launch(void* const* d_in, const int* in_sizes, int n_in,
                              void* d_out, int out_size) {
    const float* x  = (const float*)d_in[0];
    const float* w1 = (const float*)d_in[1];
    const float* b1 = (const float*)d_in[2];
    const float* w2 = (const float*)d_in[3];
    const float* b2 = (const float*)d_in[4];
    const float* rw = (const float*)d_in[5];
    const float* rb = (const float*)d_in[6];
    float* out = (float*)d_out;

    zero_counts_kernel<<<1, 32>>>();
    router_kernel<<<T_TOK / 8, 256>>>(x, rw, rb);
    scan_kernel<<<1, 1>>>();

    dim3 g1(F_DIM / BN, T_TOK / BM, NEXP);   // 32 x 64 x 8
    moe_gemm<H_DIM, 0><<<g1, 256>>>(x, w1, b1, F_DIM);

    dim3 g2(H_DIM / BN, T_TOK / BM, NEXP);   // 8 x 64 x 8
    moe_gemm<F_DIM, 1><<<g2, 256>>>(x, w2, b2, H_DIM);

    combine_kernel<<<(T_TOK * H_DIM) / 256, 256>>>(out);
}

// round 5
// speedup vs baseline: 1.9735x; 1.9735x over previous
#include <cuda_runtime.h>
#include <cuda_fp16.h>
#include <cstdint>
#include <math.h>

// Problem constants (B=4, S=2048 -> T=8192 tokens)
#define T_TOK 8192
#define H_DIM 1024
#define F_DIM 4096
#define NEXP  8

// GEMM tile: 128x128x32, fp16 mma.sync m16n8k16, 8 warps (4x2), 3-stage cp.async
#define BM 128
#define BN 128
#define BK 32
#define NSTAGE 3
#define A_STRIDE 80                   // bytes per A smem row (64 data + 16 pad) -> ldmatrix conflict-free
#define B_STRIDE 272                  // bytes per B smem row (256 data + 16 pad) -> ldmatrix conflict-free
#define A_BYTES (BM * A_STRIDE)       // 10240
#define B_BYTES (BK * B_STRIDE)       // 8704
#define STAGE_BYTES (A_BYTES + B_BYTES)
#define SM_TOTAL (NSTAGE * STAGE_BYTES)   // 56832

// ---- persistent scratch (device globals: allocation-free kernel_launch) ----
__device__ int    g_count[NEXP];
__device__ int    g_offset[NEXP];
__device__ int    g_perm[NEXP * T_TOK];
__device__ float  g_wslot[T_TOK * 2];
__device__ __half g_xh[(size_t)T_TOK * H_DIM];
__device__ __half g_w1h[(size_t)NEXP * H_DIM * F_DIM];
__device__ __half g_w2h[(size_t)NEXP * F_DIM * H_DIM];
__device__ __half g_hbuf[(size_t)T_TOK * 2 * F_DIM];   // gelu(x@w1+b1), compact fp16 rows
__device__ float  g_ybuf[(size_t)T_TOK * 2 * H_DIM];   // per-slot expert output (fp32)

// ---------------------------------------------------------------------------
__device__ __forceinline__ uint32_t smem_u32(const void* p) {
    uint32_t a;
    asm("{ .reg .u64 t; cvta.to.shared.u64 t, %1; cvt.u32.u64 %0, t; }" : "=r"(a) : "l"(p));
    return a;
}

#define CP_ASYNC16(dst, src, sz) \
    asm volatile("cp.async.cg.shared.global [%0], [%1], 16, %2;" \
                 :: "r"(dst), "l"(src), "r"(sz) : "memory")
#define CP_COMMIT()  asm volatile("cp.async.commit_group;" ::: "memory")
#define CP_WAIT2()   asm volatile("cp.async.wait_group 2;" ::: "memory")
#define CP_WAIT0()   asm volatile("cp.async.wait_group 0;" ::: "memory")

#define LDSM_X4(r0, r1, r2, r3, a) \
    asm volatile("ldmatrix.sync.aligned.m8n8.x4.shared.b16 {%0,%1,%2,%3}, [%4];" \
                 : "=r"(r0), "=r"(r1), "=r"(r2), "=r"(r3) : "r"(a))
#define LDSM_X4_T(r0, r1, r2, r3, a) \
    asm volatile("ldmatrix.sync.aligned.m8n8.x4.trans.shared.b16 {%0,%1,%2,%3}, [%4];" \
                 : "=r"(r0), "=r"(r1), "=r"(r2), "=r"(r3) : "r"(a))

#define MMA16816(c0, c1, c2, c3, a0, a1, a2, a3, b0, b1) \
    asm volatile("mma.sync.aligned.m16n8k16.row.col.f32.f16.f16.f32 " \
                 "{%0,%1,%2,%3}, {%4,%5,%6,%7}, {%8,%9}, {%0,%1,%2,%3};" \
                 : "+f"(c0), "+f"(c1), "+f"(c2), "+f"(c3) \
                 : "r"(a0), "r"(a1), "r"(a2), "r"(a3), "r"(b0), "r"(b1))

// ---------------------------------------------------------------------------
__global__ void zero_counts_kernel() {
    if (threadIdx.x < NEXP) g_count[threadIdx.x] = 0;
}
__global__ void scan_kernel() {
    int s = 0;
    for (int e = 0; e < NEXP; e++) { g_offset[e] = s; s += g_count[e]; }
}

__global__ __launch_bounds__(256)
void router_kernel(const float* __restrict__ x,
                   const float* __restrict__ rw,
                   const float* __restrict__ rb) {
    int warp = (blockIdx.x * blockDim.x + threadIdx.x) >> 5;
    int lane = threadIdx.x & 31;
    if (warp >= T_TOK) return;
    const float* xr = x + (size_t)warp * H_DIM;
    float acc[NEXP];
#pragma unroll
    for (int e = 0; e < NEXP; e++) acc[e] = 0.f;
    for (int h = lane; h < H_DIM; h += 32) {
        float xv = xr[h];
        const float* w = rw + h * NEXP;
#pragma unroll
        for (int e = 0; e < NEXP; e++) acc[e] += xv * w[e];
    }
#pragma unroll
    for (int e = 0; e < NEXP; e++)
#pragma unroll
        for (int s = 16; s > 0; s >>= 1)
            acc[e] += __shfl_xor_sync(0xffffffffu, acc[e], s);
    if (lane == 0) {
#pragma unroll
        for (int e = 0; e < NEXP; e++) acc[e] += rb[e];
        int e0 = 0;
#pragma unroll
        for (int e = 1; e < NEXP; e++) if (acc[e] > acc[e0]) e0 = e;
        int e1 = (e0 == 0) ? 1 : 0;
#pragma unroll
        for (int e = 0; e < NEXP; e++)
            if (e != e0 && acc[e] > acc[e1]) e1 = e;
        float r  = expf(acc[e1] - acc[e0]);
        float w0 = 1.f / (1.f + r);
        float w1 = r / (1.f + r);
        int s0 = warp * 2, s1 = warp * 2 + 1;
        int p0 = atomicAdd(&g_count[e0], 1);
        g_perm[e0 * T_TOK + p0] = s0;
        g_wslot[s0] = w0;
        int p1 = atomicAdd(&g_count[e1], 1);
        g_perm[e1 * T_TOK + p1] = s1;
        g_wslot[s1] = w1;
    }
}

// fp32 -> fp16 bulk convert (n4 = n/4)
__global__ __launch_bounds__(256)
void f32_to_f16_kernel(const float* __restrict__ s, __half* __restrict__ d, int n4) {
    int i = blockIdx.x * blockDim.x + threadIdx.x;
    if (i >= n4) return;
    float4 v = ((const float4*)s)[i];
    __half2* dp = (__half2*)d + 2 * (size_t)i;
    dp[0] = __floats2half2_rn(v.x, v.y);
    dp[1] = __floats2half2_rn(v.z, v.w);
}

__device__ __forceinline__ float gelu_tanh(float v) {
    float v3 = v * v * v;
    float t  = tanhf(0.7978845608028654f * (v + 0.044715f * v3));
    return 0.5f * v * (1.f + t);
}

// ---------------------------------------------------------------------------
// Gathered per-expert fp16 GEMM (mma.sync m16n8k16, ldmatrix, 3-stage cp.async)
// MODE 0: hbuf = fp16(gelu(Xgather @ w1 + b1)),  A = g_xh gathered, KD = H
// MODE 1: ybuf = hbuf @ w2 + b2 (scatter rows),  A = g_hbuf compact, KD = F
// B = W fp16, natural [KD][ND] layout (K-major rows), no transpose needed.
// ---------------------------------------------------------------------------
template<int KD, int MODE>
__global__ __launch_bounds__(256, 2)
void moe_gemm(const __half* __restrict__ Ah,
              const __half* __restrict__ W,
              const float* __restrict__ bias,
              int ND) {
    extern __shared__ __align__(128) char smem[];
    const uint32_t sb = smem_u32(smem);

    const int e    = blockIdx.z;
    const int cnt  = g_count[e];
    const int row0 = blockIdx.y * BM;
    if (row0 >= cnt) return;
    const int col0 = blockIdx.x * BN;
    const int off  = g_offset[e];

    const int tid  = threadIdx.x;
    const int lane = tid & 31, wid = tid >> 5;
    const int wm = wid & 3, wn = wid >> 2;       // 4x2 warp grid, warp tile 32x64

    // ---- cp.async staging: A 2 chunks/thread, B 2 chunks/thread (16B each) ----
    const int ar0  = tid >> 2;                   // 0..63
    const int segA = tid & 3;                    // 16B segment in 64B row
    const __half* aSrc[2]; uint32_t aDst[2], aSz[2];
#pragma unroll
    for (int i = 0; i < 2; i++) {
        int r = ar0 + 64 * i;
        bool v = (row0 + r) < cnt;
        long srow;
        if (MODE == 0) srow = v ? (long)(g_perm[e * T_TOK + row0 + r] >> 1) : 0;
        else           srow = (long)off + (v ? row0 + r : 0);
        aSrc[i] = Ah + (size_t)srow * KD + segA * 8;
        aDst[i] = (uint32_t)(r * A_STRIDE + segA * 16);
        aSz[i]  = v ? 16u : 0u;
    }
    const int br0  = tid >> 4;                   // 0..15
    const int segB = tid & 15;                   // 16B segment in 256B row
    const __half* bSrc[2]; uint32_t bDst[2];
    const __half* We = W + (size_t)e * KD * ND;
#pragma unroll
    for (int i = 0; i < 2; i++) {
        int r = br0 + 16 * i;
        bSrc[i] = We + (size_t)r * ND + col0 + segB * 8;
        bDst[i] = (uint32_t)(r * B_STRIDE + segB * 16);
    }

    auto issue_tile = [&](int kt, int st) {
        uint32_t aB = sb + st * STAGE_BYTES;
        uint32_t bB = aB + A_BYTES;
#pragma unroll
        for (int i = 0; i < 2; i++)
            CP_ASYNC16(aB + aDst[i], aSrc[i] + kt * BK, aSz[i]);
#pragma unroll
        for (int i = 0; i < 2; i++)
            CP_ASYNC16(bB + bDst[i], bSrc[i] + (size_t)kt * BK * ND, 16u);
    };

    // ---- ldmatrix fragment offsets (lane-dependent, stage-relative) ----
    int aOff[2];
#pragma unroll
    for (int mf = 0; mf < 2; mf++)
        aOff[mf] = (wm * 32 + mf * 16 + (lane & 15)) * A_STRIDE + (lane >> 4) * 16;
    const int bRow = (lane & 7) + ((lane >> 3) & 1) * 8;
    int bOff[4];
#pragma unroll
    for (int p = 0; p < 4; p++)
        bOff[p] = bRow * B_STRIDE + (wn * 64 + p * 16 + (lane >> 4) * 8) * 2;

    float c[2][8][4];
#pragma unroll
    for (int i = 0; i < 2; i++)
#pragma unroll
        for (int j = 0; j < 8; j++)
#pragma unroll
            for (int q = 0; q < 4; q++) c[i][j][q] = 0.f;

    const int nk = KD / BK;
    // prologue: stages 0..NSTAGE-2
#pragma unroll
    for (int kt = 0; kt < NSTAGE - 1; kt++) { issue_tile(kt, kt); CP_COMMIT(); }

    for (int kt = 0; kt < nk; kt++) {
        int nt = kt + NSTAGE - 1;
        if (nt < nk) issue_tile(nt, nt % NSTAGE);
        CP_COMMIT();
        CP_WAIT2();
        __syncthreads();

        uint32_t aB = sb + (kt % NSTAGE) * STAGE_BYTES;
        uint32_t bB = aB + A_BYTES;
#pragma unroll
        for (int ks = 0; ks < 2; ks++) {
            uint32_t af[2][4], bf[8][2];
#pragma unroll
            for (int mf = 0; mf < 2; mf++)
                LDSM_X4(af[mf][0], af[mf][1], af[mf][2], af[mf][3],
                        aB + aOff[mf] + ks * 32);
#pragma unroll
            for (int p = 0; p < 4; p++)
                LDSM_X4_T(bf[2 * p][0], bf[2 * p][1], bf[2 * p + 1][0], bf[2 * p + 1][1],
                          bB + bOff[p] + ks * 16 * B_STRIDE);
#pragma unroll
            for (int mf = 0; mf < 2; mf++)
#pragma unroll
                for (int nf = 0; nf < 8; nf++)
                    MMA16816(c[mf][nf][0], c[mf][nf][1], c[mf][nf][2], c[mf][nf][3],
                             af[mf][0], af[mf][1], af[mf][2], af[mf][3],
                             bf[nf][0], bf[nf][1]);
        }
        __syncthreads();
    }
    CP_WAIT0();

    // ---- epilogue: c frag rows (g, g+8), cols (2*tg, 2*tg+1) ----
    const int g  = lane >> 2, tg = lane & 3;
    const float* bz = bias + e * ND + col0;
#pragma unroll
    for (int mf = 0; mf < 2; mf++) {
#pragma unroll
        for (int hh = 0; hh < 2; hh++) {
            int r    = wm * 32 + mf * 16 + g + hh * 8;
            int grow = row0 + r;
            if (grow >= cnt) continue;
            size_t drow;
            if (MODE == 0) drow = (size_t)(off + grow) * F_DIM;
            else           drow = (size_t)g_perm[e * T_TOK + grow] * H_DIM;
#pragma unroll
            for (int nf = 0; nf < 8; nf++) {
                int cn   = wn * 64 + nf * 8 + 2 * tg;
                float v0 = c[mf][nf][hh * 2 + 0] + bz[cn];
                float v1 = c[mf][nf][hh * 2 + 1] + bz[cn + 1];
                if (MODE == 0) {
                    *(__half2*)&g_hbuf[drow + col0 + cn] =
                        __floats2half2_rn(gelu_tanh(v0), gelu_tanh(v1));
                } else {
                    *(float2*)&g_ybuf[drow + col0 + cn] = make_float2(v0, v1);
                }
            }
        }
    }
}

// ---------------------------------------------------------------------------
__global__ __launch_bounds__(256)
void combine_kernel(float* __restrict__ out) {
    int idx = blockIdx.x * blockDim.x + threadIdx.x;
    if (idx >= T_TOK * H_DIM) return;
    int t = idx >> 10;
    int h = idx & 1023;
    out[idx] = g_wslot[2 * t]     * g_ybuf[(size_t)(2 * t)     * H_DIM + h]
             + g_wslot[2 * t + 1] * g_ybuf[(size_t)(2 * t + 1) * H_DIM + h];
}

// ---------------------------------------------------------------------------
extern "C" void kernel_launch(void* const* d_in, const int* in_sizes, int n_in,
                              void* d_out, int out_size) {
    const float* x  = (const float*)d_in[0];
    const float* w1 = (const float*)d_in[1];
    const float* b1 = (const float*)d_in[2];
    const float* w2 = (const float*)d_in[3];
    const float* b2 = (const float*)d_in[4];
    const float* rw = (const float*)d_in[5];
    const float* rb = (const float*)d_in[6];
    float* out = (float*)d_out;

    cudaFuncSetAttribute(moe_gemm<H_DIM, 0>, cudaFuncAttributeMaxDynamicSharedMemorySize, SM_TOTAL);
    cudaFuncSetAttribute(moe_gemm<F_DIM, 1>, cudaFuncAttributeMaxDynamicSharedMemorySize, SM_TOTAL);

    zero_counts_kernel<<<1, 32>>>();
    router_kernel<<<T_TOK / 8, 256>>>(x, rw, rb);
    scan_kernel<<<1, 1>>>();

    // fp32 -> fp16 pre-conversion (x, w1, w2)
    {
        __half *xh, *w1h, *w2h;
        cudaGetSymbolAddress((void**)&xh,  g_xh);
        cudaGetSymbolAddress((void**)&w1h, g_w1h);
        cudaGetSymbolAddress((void**)&w2h, g_w2h);
        int nx = T_TOK * H_DIM / 4;
        int nw = NEXP * H_DIM * F_DIM / 4;
        f32_to_f16_kernel<<<(nx + 255) / 256, 256>>>(x,  xh,  nx);
        f32_to_f16_kernel<<<(nw + 255) / 256, 256>>>(w1, w1h, nw);
        f32_to_f16_kernel<<<(nw + 255) / 256, 256>>>(w2, w2h, nw);
    }

    __half *xh, *w1h, *w2h, *hb;
    cudaGetSymbolAddress((void**)&xh,  g_xh);
    cudaGetSymbolAddress((void**)&w1h, g_w1h);
    cudaGetSymbolAddress((void**)&w2h, g_w2h);
    cudaGetSymbolAddress((void**)&hb,  g_hbuf);

    dim3 g1(F_DIM / BN, T_TOK / BM, NEXP);   // 32 x 64 x 8
    moe_gemm<H_DIM, 0><<<g1, 256, SM_TOTAL>>>(xh, w1h, b1, F_DIM);

    dim3 g2(H_DIM / BN, T_TOK / BM, NEXP);   // 8 x 64 x 8
    moe_gemm<F_DIM, 1><<<g2, 256, SM_TOTAL>>>(hb, w2h, b2, H_DIM);

    combine_kernel<<<(T_TOK * H_DIM) / 256, 256>>>(out);
}

// round 11
// speedup vs baseline: 2.2278x; 1.1289x over previous
#include <cuda_runtime.h>
#include <cuda_fp16.h>
#include <cstdint>
#include <math.h>

// Problem constants (B=4, S=2048 -> T=8192 tokens)
#define T_TOK 8192
#define H_DIM 1024
#define F_DIM 4096
#define NEXP  8

// GEMM tile: 128x128x64, fp16 mma.sync m16n8k16, 8 warps (4x2),
// 3-stage cp.async, ONE __syncthreads per K-iteration.
#define BM 128
#define BN 128
#define BK 64
#define NSTAGE 3
#define A_STRIDE 144                  // bytes per A smem row (128 data + 16 pad)
#define B_STRIDE 272                  // bytes per B smem row (256 data + 16 pad)
#define A_BYTES (BM * A_STRIDE)       // 18432
#define B_BYTES (BK * B_STRIDE)       // 17408
#define STAGE_BYTES (A_BYTES + B_BYTES)   // 35840
#define SM_TOTAL (NSTAGE * STAGE_BYTES)   // 107520

// ---- persistent scratch (device globals: allocation-free kernel_launch) ----
__device__ int    g_count[NEXP];
__device__ int    g_offset[NEXP];
__device__ int    g_perm[NEXP * T_TOK];
__device__ float  g_wslot[T_TOK * 2];
__device__ __half g_xh[(size_t)T_TOK * H_DIM];
__device__ __half g_w1h[(size_t)NEXP * H_DIM * F_DIM];
__device__ __half g_w2h[(size_t)NEXP * F_DIM * H_DIM];
__device__ __half g_hbuf[(size_t)T_TOK * 2 * F_DIM];   // gelu(x@w1+b1), compact fp16 rows
__device__ float  g_ybuf[(size_t)T_TOK * 2 * H_DIM];   // per-slot expert output (fp32)

// ---------------------------------------------------------------------------
__device__ __forceinline__ uint32_t smem_u32(const void* p) {
    uint32_t a;
    asm("{ .reg .u64 t; cvta.to.shared.u64 t, %1; cvt.u32.u64 %0, t; }" : "=r"(a) : "l"(p));
    return a;
}

#define CP_ASYNC16(dst, src, sz) \
    asm volatile("cp.async.cg.shared.global [%0], [%1], 16, %2;" \
                 :: "r"(dst), "l"(src), "r"(sz) : "memory")
#define CP_COMMIT()  asm volatile("cp.async.commit_group;" ::: "memory")
#define CP_WAIT1()   asm volatile("cp.async.wait_group 1;" ::: "memory")
#define CP_WAIT0()   asm volatile("cp.async.wait_group 0;" ::: "memory")

#define LDSM_X4(r0, r1, r2, r3, a) \
    asm volatile("ldmatrix.sync.aligned.m8n8.x4.shared.b16 {%0,%1,%2,%3}, [%4];" \
                 : "=r"(r0), "=r"(r1), "=r"(r2), "=r"(r3) : "r"(a))
#define LDSM_X4_T(r0, r1, r2, r3, a) \
    asm volatile("ldmatrix.sync.aligned.m8n8.x4.trans.shared.b16 {%0,%1,%2,%3}, [%4];" \
                 : "=r"(r0), "=r"(r1), "=r"(r2), "=r"(r3) : "r"(a))

#define MMA16816(c0, c1, c2, c3, a0, a1, a2, a3, b0, b1) \
    asm volatile("mma.sync.aligned.m16n8k16.row.col.f32.f16.f16.f32 " \
                 "{%0,%1,%2,%3}, {%4,%5,%6,%7}, {%8,%9}, {%0,%1,%2,%3};" \
                 : "+f"(c0), "+f"(c1), "+f"(c2), "+f"(c3) \
                 : "r"(a0), "r"(a1), "r"(a2), "r"(a3), "r"(b0), "r"(b1))

// ---------------------------------------------------------------------------
__global__ void zero_counts_kernel() {
    if (threadIdx.x < NEXP) g_count[threadIdx.x] = 0;
}
__global__ void scan_kernel() {
    int s = 0;
    for (int e = 0; e < NEXP; e++) { g_offset[e] = s; s += g_count[e]; }
}

// Router (one warp/token) + fused x -> fp16 conversion (x is streamed anyway).
__global__ __launch_bounds__(256)
void router_kernel(const float* __restrict__ x,
                   const float* __restrict__ rw,
                   const float* __restrict__ rb) {
    int warp = (blockIdx.x * blockDim.x + threadIdx.x) >> 5;
    int lane = threadIdx.x & 31;
    if (warp >= T_TOK) return;
    const float* xr = x + (size_t)warp * H_DIM;
    __half* xo = g_xh + (size_t)warp * H_DIM;
    float acc[NEXP];
#pragma unroll
    for (int e = 0; e < NEXP; e++) acc[e] = 0.f;
    for (int h = lane; h < H_DIM; h += 32) {
        float xv = xr[h];
        xo[h] = __float2half_rn(xv);
        const float* w = rw + h * NEXP;
#pragma unroll
        for (int e = 0; e < NEXP; e++) acc[e] += xv * w[e];
    }
#pragma unroll
    for (int e = 0; e < NEXP; e++)
#pragma unroll
        for (int s = 16; s > 0; s >>= 1)
            acc[e] += __shfl_xor_sync(0xffffffffu, acc[e], s);
    if (lane == 0) {
#pragma unroll
        for (int e = 0; e < NEXP; e++) acc[e] += rb[e];
        int e0 = 0;
#pragma unroll
        for (int e = 1; e < NEXP; e++) if (acc[e] > acc[e0]) e0 = e;
        int e1 = (e0 == 0) ? 1 : 0;
#pragma unroll
        for (int e = 0; e < NEXP; e++)
            if (e != e0 && acc[e] > acc[e1]) e1 = e;
        float r  = expf(acc[e1] - acc[e0]);
        float w0 = 1.f / (1.f + r);
        float w1 = r / (1.f + r);
        int s0 = warp * 2, s1 = warp * 2 + 1;
        int p0 = atomicAdd(&g_count[e0], 1);
        g_perm[e0 * T_TOK + p0] = s0;
        g_wslot[s0] = w0;
        int p1 = atomicAdd(&g_count[e1], 1);
        g_perm[e1 * T_TOK + p1] = s1;
        g_wslot[s1] = w1;
    }
}

// Streaming fp32 -> fp16 convert, grid-stride, float4 -> 8B per step.
__global__ __launch_bounds__(256)
void f32_to_f16_kernel(const float* __restrict__ s, __half* __restrict__ d, int n4) {
    int stride = gridDim.x * blockDim.x;
    for (int i = blockIdx.x * blockDim.x + threadIdx.x; i < n4; i += stride) {
        float4 v = __ldcs((const float4*)s + i);
        __half2 h0 = __floats2half2_rn(v.x, v.y);
        __half2 h1 = __floats2half2_rn(v.z, v.w);
        uint2 o = make_uint2(*reinterpret_cast<uint32_t*>(&h0),
                             *reinterpret_cast<uint32_t*>(&h1));
        __stcs((uint2*)d + i, o);
    }
}

__device__ __forceinline__ float gelu_tanh(float v) {
    float v3 = v * v * v;
    float t  = tanhf(0.7978845608028654f * (v + 0.044715f * v3));
    return 0.5f * v * (1.f + t);
}

// ---------------------------------------------------------------------------
// Gathered per-expert fp16 GEMM (mma.sync m16n8k16, ldmatrix, 3-stage cp.async,
// one barrier per K-iteration).
// MODE 0: hbuf = fp16(gelu(Xgather @ w1 + b1)),  A = g_xh gathered, KD = H
// MODE 1: ybuf = hbuf @ w2 + b2 (scatter rows),  A = g_hbuf compact, KD = F
// ---------------------------------------------------------------------------
template<int KD, int MODE>
__global__ __launch_bounds__(256, 2)
void moe_gemm(const __half* __restrict__ Ah,
              const __half* __restrict__ W,
              const float* __restrict__ bias,
              int ND) {
    extern __shared__ __align__(128) char smem[];
    const uint32_t sb = smem_u32(smem);

    const int e    = blockIdx.z;
    const int cnt  = g_count[e];
    const int row0 = blockIdx.y * BM;
    if (row0 >= cnt) return;
    const int col0 = blockIdx.x * BN;
    const int off  = g_offset[e];

    const int tid  = threadIdx.x;
    const int lane = tid & 31, wid = tid >> 5;
    const int wm = wid & 3, wn = wid >> 2;       // 4x2 warp grid, warp tile 32x64

    // ---- cp.async staging ----
    // A: 128 rows x 128B data (A_STRIDE pad). 8 segs/row; thread -> 4 rows.
    const int segA = tid & 7;
    const int ar0  = tid >> 3;                   // 0..31
    const __half* aSrc[4]; uint32_t aDst[4], aSz[4];
#pragma unroll
    for (int i = 0; i < 4; i++) {
        int r = ar0 + 32 * i;
        bool v = (row0 + r) < cnt;
        long srow;
        if (MODE == 0) srow = v ? (long)(g_perm[e * T_TOK + row0 + r] >> 1) : 0;
        else           srow = (long)off + (v ? row0 + r : 0);
        aSrc[i] = Ah + (size_t)srow * KD + segA * 8;
        aDst[i] = (uint32_t)(r * A_STRIDE + segA * 16);
        aSz[i]  = v ? 16u : 0u;
    }
    // B: 64 rows x 256B data (B_STRIDE pad). 16 segs/row; thread -> 4 rows.
    const int segB = tid & 15;
    const int br0  = tid >> 4;                   // 0..15
    const __half* bSrc[4]; uint32_t bDst[4];
    const __half* We = W + (size_t)e * KD * ND;
#pragma unroll
    for (int i = 0; i < 4; i++) {
        int r = br0 + 16 * i;
        bSrc[i] = We + (size_t)r * ND + col0 + segB * 8;
        bDst[i] = (uint32_t)(r * B_STRIDE + segB * 16);
    }

    auto issue_tile = [&](int kt, int st) {
        uint32_t aB = sb + st * STAGE_BYTES;
        uint32_t bB = aB + A_BYTES;
#pragma unroll
        for (int i = 0; i < 4; i++)
            CP_ASYNC16(aB + aDst[i], aSrc[i] + kt * BK, aSz[i]);
#pragma unroll
        for (int i = 0; i < 4; i++)
            CP_ASYNC16(bB + bDst[i], bSrc[i] + (size_t)kt * BK * ND, 16u);
    };

    // ---- ldmatrix fragment offsets ----
    int aOff[2];
#pragma unroll
    for (int mf = 0; mf < 2; mf++)
        aOff[mf] = (wm * 32 + mf * 16 + (lane & 15)) * A_STRIDE + (lane >> 4) * 16;
    const int bRow = (lane & 7) + ((lane >> 3) & 1) * 8;
    int bOff[4];
#pragma unroll
    for (int p = 0; p < 4; p++)
        bOff[p] = bRow * B_STRIDE + (wn * 64 + p * 16 + (lane >> 4) * 8) * 2;

    float c[2][8][4];
#pragma unroll
    for (int i = 0; i < 2; i++)
#pragma unroll
        for (int j = 0; j < 8; j++)
#pragma unroll
            for (int q = 0; q < 4; q++) c[i][j][q] = 0.f;

    const int nk = KD / BK;
    // prologue: tiles 0..NSTAGE-2
#pragma unroll
    for (int kt = 0; kt < NSTAGE - 1; kt++) { issue_tile(kt, kt); CP_COMMIT(); }

    for (int kt = 0; kt < nk; kt++) {
        CP_WAIT1();                // tile kt landed (<=1 group outstanding)
        __syncthreads();           // all threads see it; stage (kt-1)%3 now free
        int nt = kt + NSTAGE - 1;
        if (nt < nk) { issue_tile(nt, nt % NSTAGE); CP_COMMIT(); }

        uint32_t aB = sb + (kt % NSTAGE) * STAGE_BYTES;
        uint32_t bB = aB + A_BYTES;
#pragma unroll
        for (int ks = 0; ks < 4; ks++) {       // 4 x K=16 = BK
            uint32_t af[2][4], bf[8][2];
#pragma unroll
            for (int mf = 0; mf < 2; mf++)
                LDSM_X4(af[mf][0], af[mf][1], af[mf][2], af[mf][3],
                        aB + aOff[mf] + ks * 32);
#pragma unroll
            for (int p = 0; p < 4; p++)
                LDSM_X4_T(bf[2 * p][0], bf[2 * p][1], bf[2 * p + 1][0], bf[2 * p + 1][1],
                          bB + bOff[p] + ks * 16 * B_STRIDE);
#pragma unroll
            for (int mf = 0; mf < 2; mf++)
#pragma unroll
                for (int nf = 0; nf < 8; nf++)
                    MMA16816(c[mf][nf][0], c[mf][nf][1], c[mf][nf][2], c[mf][nf][3],
                             af[mf][0], af[mf][1], af[mf][2], af[mf][3],
                             bf[nf][0], bf[nf][1]);
        }
    }
    CP_WAIT0();

    // ---- epilogue: c frag rows (g, g+8), cols (2*tg, 2*tg+1) ----
    const int g  = lane >> 2, tg = lane & 3;
    const float* bz = bias + e * ND + col0;
#pragma unroll
    for (int mf = 0; mf < 2; mf++) {
#pragma unroll
        for (int hh = 0; hh < 2; hh++) {
            int r    = wm * 32 + mf * 16 + g + hh * 8;
            int grow = row0 + r;
            if (grow >= cnt) continue;
            size_t drow;
            if (MODE == 0) drow = (size_t)(off + grow) * F_DIM;
            else           drow = (size_t)g_perm[e * T_TOK + grow] * H_DIM;
#pragma unroll
            for (int nf = 0; nf < 8; nf++) {
                int cn   = wn * 64 + nf * 8 + 2 * tg;
                float v0 = c[mf][nf][hh * 2 + 0] + bz[cn];
                float v1 = c[mf][nf][hh * 2 + 1] + bz[cn + 1];
                if (MODE == 0) {
                    *(__half2*)&g_hbuf[drow + col0 + cn] =
                        __floats2half2_rn(gelu_tanh(v0), gelu_tanh(v1));
                } else {
                    *(float2*)&g_ybuf[drow + col0 + cn] = make_float2(v0, v1);
                }
            }
        }
    }
}

// ---------------------------------------------------------------------------
__global__ __launch_bounds__(256)
void combine_kernel(float* __restrict__ out) {
    int idx = blockIdx.x * blockDim.x + threadIdx.x;
    if (idx >= T_TOK * H_DIM) return;
    int t = idx >> 10;
    int h = idx & 1023;
    out[idx] = g_wslot[2 * t]     * g_ybuf[(size_t)(2 * t)     * H_DIM + h]
             + g_wslot[2 * t + 1] * g_ybuf[(size_t)(2 * t + 1) * H_DIM + h];
}

// ---------------------------------------------------------------------------
extern "C" void kernel_launch(void* const* d_in, const int* in_sizes, int n_in,
                              void* d_out, int out_size) {
    const float* x  = (const float*)d_in[0];
    const float* w1 = (const float*)d_in[1];
    const float* b1 = (const float*)d_in[2];
    const float* w2 = (const float*)d_in[3];
    const float* b2 = (const float*)d_in[4];
    const float* rw = (const float*)d_in[5];
    const float* rb = (const float*)d_in[6];
    float* out = (float*)d_out;

    cudaFuncSetAttribute(moe_gemm<H_DIM, 0>, cudaFuncAttributeMaxDynamicSharedMemorySize, SM_TOTAL);
    cudaFuncSetAttribute(moe_gemm<F_DIM, 1>, cudaFuncAttributeMaxDynamicSharedMemorySize, SM_TOTAL);

    zero_counts_kernel<<<1, 32>>>();
    router_kernel<<<T_TOK / 8, 256>>>(x, rw, rb);   // also emits g_xh (fp16)
    scan_kernel<<<1, 1>>>();

    // fp32 -> fp16 weight conversion (grid-stride streaming)
    __half *w1h, *w2h, *xh, *hb;
    cudaGetSymbolAddress((void**)&w1h, g_w1h);
    cudaGetSymbolAddress((void**)&w2h, g_w2h);
    cudaGetSymbolAddress((void**)&xh,  g_xh);
    cudaGetSymbolAddress((void**)&hb,  g_hbuf);
    {
        int nw = NEXP * H_DIM * F_DIM / 4;
        f32_to_f16_kernel<<<2048, 256>>>(w1, w1h, nw);
        f32_to_f16_kernel<<<2048, 256>>>(w2, w2h, nw);
    }

    dim3 g1(F_DIM / BN, T_TOK / BM, NEXP);   // 32 x 64 x 8
    moe_gemm<H_DIM, 0><<<g1, 256, SM_TOTAL>>>(xh, w1h, b1, F_DIM);

    dim3 g2(H_DIM / BN, T_TOK / BM, NEXP);   // 8 x 64 x 8
    moe_gemm<F_DIM, 1><<<g2, 256, SM_TOTAL>>>(hb, w2h, b2, H_DIM);

    combine_kernel<<<(T_TOK * H_DIM) / 256, 256>>>(out);
}